// round 1
// baseline (speedup 1.0000x reference)
#include <cuda_runtime.h>
#include <cuda_bf16.h>
#include <cstddef>

#define E_TOT 512
#define Dd    64
#define Hh    256
#define Nn    16
#define Aa    8
#define Tt    128
#define RPB   8          // MLP rows per block

#define SF2   0.01f
#define SN2   0.01f
#define NEG_HALF_INV_L2 (-50.0f)   // -0.5 / 0.1^2

// scratch (no allocation allowed -> device globals)
__device__ float g_times[E_TOT * Nn];
__device__ float g_anchors[E_TOT * Aa * Nn];

// ---------------------------------------------------------------------------
// Kernel 1: MLP. 64 blocks x 8 rows, 256 threads. thread = output column.
// ---------------------------------------------------------------------------
__global__ __launch_bounds__(256)
void mlp_kernel(const float* __restrict__ x,
                const float* __restrict__ W1, const float* __restrict__ b1,
                const float* __restrict__ W2, const float* __restrict__ b2,
                const float* __restrict__ Wt, const float* __restrict__ bt,
                const float* __restrict__ Wa, const float* __restrict__ ba)
{
    __shared__ float xs[RPB][Dd];
    __shared__ float h1[RPB][Hh];
    __shared__ float h2[RPB][Hh];

    const int e0  = blockIdx.x * RPB;
    const int tid = threadIdx.x;

    for (int idx = tid; idx < RPB * Dd; idx += 256) {
        int r = idx / Dd, k = idx % Dd;
        xs[r][k] = x[(e0 + r) * Dd + k];
    }
    __syncthreads();

    // layer 1: h1[r][tid] = tanh(dot(W1[tid], x[r]) + b1[tid])
    {
        float acc[RPB];
        float bias = b1[tid];
        #pragma unroll
        for (int r = 0; r < RPB; r++) acc[r] = bias;
        const float* w = W1 + tid * Dd;
        for (int k = 0; k < Dd; k += 4) {
            float4 w4 = *(const float4*)(w + k);
            #pragma unroll
            for (int r = 0; r < RPB; r++) {
                float4 x4 = *(const float4*)&xs[r][k];
                acc[r] += w4.x * x4.x + w4.y * x4.y + w4.z * x4.z + w4.w * x4.w;
            }
        }
        #pragma unroll
        for (int r = 0; r < RPB; r++) h1[r][tid] = tanhf(acc[r]);
    }
    __syncthreads();

    // layer 2
    {
        float acc[RPB];
        float bias = b2[tid];
        #pragma unroll
        for (int r = 0; r < RPB; r++) acc[r] = bias;
        const float* w = W2 + tid * Hh;
        for (int k = 0; k < Hh; k += 4) {
            float4 w4 = *(const float4*)(w + k);
            #pragma unroll
            for (int r = 0; r < RPB; r++) {
                float4 h4 = *(const float4*)&h1[r][k];
                acc[r] += w4.x * h4.x + w4.y * h4.y + w4.z * h4.z + w4.w * h4.w;
            }
        }
        #pragma unroll
        for (int r = 0; r < RPB; r++) h2[r][tid] = tanhf(acc[r]);
    }
    __syncthreads();

    // heads: cols 0..15 -> times, 16..143 -> anchors
    if (tid < Nn + Aa * Nn) {
        const float* w;
        float bias;
        if (tid < Nn) { w = Wt + tid * Hh;        bias = bt[tid]; }
        else          { w = Wa + (tid - Nn) * Hh; bias = ba[tid - Nn]; }
        float acc[RPB];
        #pragma unroll
        for (int r = 0; r < RPB; r++) acc[r] = bias;
        for (int k = 0; k < Hh; k += 4) {
            float4 w4 = *(const float4*)(w + k);
            #pragma unroll
            for (int r = 0; r < RPB; r++) {
                float4 h4 = *(const float4*)&h2[r][k];
                acc[r] += w4.x * h4.x + w4.y * h4.y + w4.z * h4.z + w4.w * h4.w;
            }
        }
        #pragma unroll
        for (int r = 0; r < RPB; r++) {
            if (tid < Nn) g_times[(e0 + r) * Nn + tid] = acc[r];
            else          g_anchors[(e0 + r) * (Aa * Nn) + (tid - Nn)] = acc[r];
        }
    }
}

// ---------------------------------------------------------------------------
// Kernel 2: GP per environment e. 512 blocks, 256 threads.
//   cov depends only on t (shared across A anchors) -> compute once, write 8x.
// ---------------------------------------------------------------------------
__global__ __launch_bounds__(256)
void gp_kernel(const float* __restrict__ tq_g,
               float* __restrict__ out_mu,
               float* __restrict__ out_cov)
{
    __shared__ float tq[Tt];
    __shared__ float kssd[Tt];               // Kss[i][j] == kssd[|i-j|]
    __shared__ float tt[Nn];
    __shared__ float ys[Aa][Nn];
    __shared__ float Aug[Nn][2 * Nn + 1];    // [K | I] -> [I | K^-1], pad 33
    __shared__ float colk[Nn];
    __shared__ float St[Nn][Tt + 4];         // Ks transposed: St[n][j], pad 132
    __shared__ float U[Tt][Nn + 1];          // U = Ks @ K^-1, pad 17

    const int e   = blockIdx.x;
    const int tid = threadIdx.x;

    if (tid < Tt) tq[tid] = tq_g[tid];
    if (tid < Nn) tt[tid] = g_times[e * Nn + tid];
    if (tid >= 128 && tid < 128 + Aa * Nn) {
        int q = tid - 128;
        ys[q >> 4][q & 15] = g_anchors[e * (Aa * Nn) + q];
    }
    __syncthreads();

    if (tid < Tt) {
        float d = tq[tid] - tq[0];
        kssd[tid] = SF2 * __expf(NEG_HALF_INV_L2 * d * d);
    }
    // build [K + sn2 I | I]  (exactly 256 entries of K)
    {
        int i = tid >> 4, j = tid & 15;
        float d = tt[i] - tt[j];
        float v = SF2 * __expf(NEG_HALF_INV_L2 * d * d);
        if (i == j) v += SN2;
        Aug[i][j] = v;
        Aug[i][Nn + j] = (i == j) ? 1.0f : 0.0f;
    }
    __syncthreads();

    // Gauss-Jordan (SPD, no pivoting needed, cond(K) <= 17)
    for (int k = 0; k < Nn; k++) {
        float pinv = 1.0f / Aug[k][k];
        __syncthreads();
        if (tid < 32) Aug[k][tid] *= pinv;
        if (tid >= 32 && tid < 48) colk[tid - 32] = Aug[tid - 32][k];
        __syncthreads();
        {
            int idx = tid;            // 512 elements, 256 threads, 2 each
            int i0 = idx >> 5, j0 = idx & 31;
            if (i0 != k) Aug[i0][j0] -= colk[i0] * Aug[k][j0];
            idx += 256;
            int i1 = idx >> 5, j1 = idx & 31;
            if (i1 != k) Aug[i1][j1] -= colk[i1] * Aug[k][j1];
        }
        __syncthreads();
    }

    // Ks transposed: St[n][j] = sf2 * exp(-0.5 (tq[j]-t[n])^2 / l2)
    for (int idx = tid; idx < Tt * Nn; idx += 256) {
        int j = idx >> 4, n = idx & 15;
        float d = tq[j] - tt[n];
        St[n][j] = SF2 * __expf(NEG_HALF_INV_L2 * d * d);
    }
    __syncthreads();

    // U[i][n] = sum_m Ks[i][m] * Kinv[m][n]
    for (int idx = tid; idx < Tt * Nn; idx += 256) {
        int i = idx >> 4, n = idx & 15;
        float s = 0.0f;
        #pragma unroll
        for (int m = 0; m < Nn; m++) s += St[m][i] * Aug[m][Nn + n];
        U[i][n] = s;
    }
    __syncthreads();

    // mu[a][i] = sum_n U[i][n] * y[a][n]
    for (int idx = tid; idx < Aa * Tt; idx += 256) {
        int a = idx >> 7, i = idx & 127;
        float s = 0.0f;
        #pragma unroll
        for (int n = 0; n < Nn; n++) s += U[i][n] * ys[a][n];
        out_mu[((size_t)e * Aa + a) * Tt + i] = s;
    }

    // cov[i][j] = kssd[|i-j|] - dot16(U[i], Ks[j]); written 8x (one per anchor)
    const int lane = tid & 31;
    const int grp  = tid >> 5;
    const int j0   = lane * 4;
    for (int step = 0; step < Tt / 8; step++) {
        int i = step * 8 + grp;
        float u[Nn];
        #pragma unroll
        for (int n = 0; n < Nn; n++) u[n] = U[i][n];   // broadcast LDS
        float a0 = 0.f, a1 = 0.f, a2 = 0.f, a3 = 0.f;
        #pragma unroll
        for (int n = 0; n < Nn; n++) {
            float4 s4 = *(const float4*)&St[n][j0];    // conflict-free LDS.128
            float un = u[n];
            a0 += un * s4.x; a1 += un * s4.y; a2 += un * s4.z; a3 += un * s4.w;
        }
        int d0 = i - j0;       d0 = d0 < 0 ? -d0 : d0;
        int d1 = i - (j0 + 1); d1 = d1 < 0 ? -d1 : d1;
        int d2 = i - (j0 + 2); d2 = d2 < 0 ? -d2 : d2;
        int d3 = i - (j0 + 3); d3 = d3 < 0 ? -d3 : d3;
        float4 v;
        v.x = kssd[d0] - a0;
        v.y = kssd[d1] - a1;
        v.z = kssd[d2] - a2;
        v.w = kssd[d3] - a3;
        size_t base = (((size_t)e * Aa) * Tt + i) * Tt + j0;
        #pragma unroll
        for (int a = 0; a < Aa; a++) {
            *(float4*)&out_cov[base + (size_t)a * Tt * Tt] = v;   // coalesced STG.128
        }
    }
}

// ---------------------------------------------------------------------------
extern "C" void kernel_launch(void* const* d_in, const int* in_sizes, int n_in,
                              void* d_out, int out_size)
{
    const float* x  = (const float*)d_in[0];
    // d_in[1] = a, d_in[2] = da (unused by reference)
    const float* W1 = (const float*)d_in[3];
    const float* b1 = (const float*)d_in[4];
    const float* W2 = (const float*)d_in[5];
    const float* b2 = (const float*)d_in[6];
    const float* Wt = (const float*)d_in[7];
    const float* bt = (const float*)d_in[8];
    const float* Wa = (const float*)d_in[9];
    const float* ba = (const float*)d_in[10];
    const float* tq = (const float*)d_in[11];

    float* out     = (float*)d_out;
    float* out_mu  = out;                                   // E*A*T floats
    float* out_cov = out + (size_t)E_TOT * Aa * Tt;         // E*A*T*T floats

    mlp_kernel<<<E_TOT / RPB, 256>>>(x, W1, b1, W2, b2, Wt, bt, Wa, ba);
    gp_kernel<<<E_TOT, 256>>>(tq, out_mu, out_cov);
}